// round 1
// baseline (speedup 1.0000x reference)
#include <cuda_runtime.h>
#include <cstdint>

// One thread per batch. All weights staged in shared memory (broadcast LDS).
// Output layout: [recon (nb*8)] [lat (nb*16)] [A (nb*64)]

constexpr int NN = 8;
constexpr int BLOCK = 128;

__device__ __forceinline__ constexpr int PIDX(int i, int j) { // i<j, 0..27
    return i * 7 - (i * (i - 1)) / 2 + (j - i - 1);
}

#define AH(i, j) ((i) == (j) ? adiag[(i)] \
    : atr[PIDX(((i) < (j) ? (i) : (j)), ((i) < (j) ? (j) : (i)))])

__global__ void __launch_bounds__(BLOCK)
gae_kernel(const float* __restrict__ x, const float* __restrict__ noise,
           const float* __restrict__ We1, const float* __restrict__ be1,
           const float* __restrict__ We2, const float* __restrict__ be2,
           const float* __restrict__ Wg1, const float* __restrict__ bg1,
           const float* __restrict__ Wg2, const float* __restrict__ bg2,
           const float* __restrict__ Wd1, const float* __restrict__ bd1,
           const float* __restrict__ Wd2, const float* __restrict__ bd2,
           float* __restrict__ out, int nb)
{
    // encoder packed: (w1, w2, be1, we2_col0), we2_col1 separate
    __shared__ float4 sencA[64];
    __shared__ float  se1[64];
    __shared__ float  sg10[32], sg11[32], sbg1[32];
    __shared__ float  sWg2[32 * 32], sbg2[32];
    __shared__ float  sWd1T[64 * 32];   // transposed: [e][d]
    __shared__ float  sbd1[64], swd2[64];
    __shared__ float  sbd2;

    const int t = threadIdx.x;
    if (t < 64) {
        float4 p;
        p.x = We1[64 + t];      // row 1 (x coeff)
        p.y = We1[128 + t];     // row 2 (idx coeff)
        p.z = be1[t];
        p.w = We2[2 * t];
        sencA[t] = p;
        se1[t]   = We2[2 * t + 1];
        sbd1[t]  = bd1[t];
        swd2[t]  = Wd2[3 * t + 1];
    }
    if (t < 32) {
        sg10[t] = Wg1[t];
        sg11[t] = Wg1[32 + t];
        sbg1[t] = bg1[t];
        sbg2[t] = bg2[t];
    }
    for (int idx = t; idx < 1024; idx += BLOCK) sWg2[idx] = Wg2[idx];
    for (int idx = t; idx < 2048; idx += BLOCK) {
        int d = idx >> 6, e = idx & 63;
        sWd1T[e * 32 + d] = Wd1[idx];
    }
    if (t == 0) sbd2 = bd2[1];
    __syncthreads();

    const int b = blockIdx.x * BLOCK + t;
    if (b >= nb) return;

    float* out_recon = out;
    float* out_lat   = out + (size_t)nb * 8;
    float* out_A     = out + (size_t)nb * 24;

    // ---------------- encoder ----------------
    float xv[8];
    {
        const float4* xp = (const float4*)(x + (size_t)b * 8);
        float4 a = xp[0], c = xp[1];
        xv[0] = a.x; xv[1] = a.y; xv[2] = a.z; xv[3] = a.w;
        xv[4] = c.x; xv[5] = c.y; xv[6] = c.z; xv[7] = c.w;
    }
    float l0[8], l1[8];
    #pragma unroll
    for (int i = 0; i < 8; i++) { l0[i] = 0.0f; l1[i] = 0.0f; }

    for (int k = 0; k < 64; k++) {
        float4 p = sencA[k];
        float e1 = se1[k];
        #pragma unroll
        for (int i = 0; i < 8; i++) {
            float pre = fmaf(xv[i], p.x, fmaf((float)i, p.y, p.z));
            float h   = fmaxf(pre, 0.0f);
            l0[i] = fmaf(h, p.w, l0[i]);
            l1[i] = fmaf(h, e1,  l1[i]);
        }
    }

    // ---------------- center / std / noise ----------------
    float mu0 = 0.0f, mu1 = 0.0f;
    #pragma unroll
    for (int i = 0; i < 8; i++) { mu0 += l0[i]; mu1 += l1[i]; }
    mu0 *= 0.125f; mu1 *= 0.125f;

    float v0 = 0.0f, v1 = 0.0f;
    #pragma unroll
    for (int i = 0; i < 8; i++) {
        float c0 = l0[i] - mu0, c1 = l1[i] - mu1;
        v0 += c0 * c0; v1 += c1 * c1;
    }
    float sc0 = 3.0f / (sqrtf(v0 * (1.0f / 7.0f)) + 1e-8f);
    float sc1 = 3.0f / (sqrtf(v1 * (1.0f / 7.0f)) + 1e-8f);

    float nz[16];
    {
        const float4* np = (const float4*)(noise + (size_t)b * 16);
        float4 q0 = np[0], q1 = np[1], q2 = np[2], q3 = np[3];
        nz[0]=q0.x; nz[1]=q0.y; nz[2]=q0.z; nz[3]=q0.w;
        nz[4]=q1.x; nz[5]=q1.y; nz[6]=q1.z; nz[7]=q1.w;
        nz[8]=q2.x; nz[9]=q2.y; nz[10]=q2.z; nz[11]=q2.w;
        nz[12]=q3.x; nz[13]=q3.y; nz[14]=q3.z; nz[15]=q3.w;
    }
    float px[8], py[8];
    #pragma unroll
    for (int i = 0; i < 8; i++) {
        px[i] = ((l0[i] - mu0) * sc0) + nz[2 * i]     * 0.05f;
        py[i] = ((l1[i] - mu1) * sc1) + nz[2 * i + 1] * 0.05f;
    }

    // lat output
    {
        float4* lp = (float4*)(out_lat + (size_t)b * 16);
        #pragma unroll
        for (int q = 0; q < 4; q++) {
            float4 o;
            o.x = px[2 * q];     o.y = py[2 * q];
            o.z = px[2 * q + 1]; o.w = py[2 * q + 1];
            lp[q] = o;
        }
    }

    // ---------------- Gabriel graph ----------------
    unsigned am = 0;
    int deg[8];
    #pragma unroll
    for (int i = 0; i < 8; i++) deg[i] = 1;  // self loop

    #pragma unroll
    for (int i = 0; i < 8; i++) {
        #pragma unroll
        for (int j = i + 1; j < 8; j++) {
            float mx = (px[i] + px[j]) * 0.5f;
            float my = (py[i] + py[j]) * 0.5f;
            float dx = px[i] - mx, dy = py[i] - my;
            float r2 = dx * dx + dy * dy;
            float mind2 = 3.402823e38f;
            #pragma unroll
            for (int k = 0; k < 8; k++) {
                if (k != i && k != j) {
                    float ax = px[k] - mx, ay = py[k] - my;
                    mind2 = fminf(mind2, ax * ax + ay * ay);
                }
            }
            if (mind2 >= r2) {
                am |= (1u << PIDX(i, j));
                deg[i]++; deg[j]++;
            }
        }
    }

    float dinv[8], adiag[8];
    #pragma unroll
    for (int i = 0; i < 8; i++) {
        dinv[i]  = rsqrtf((float)deg[i]);
        adiag[i] = dinv[i] * dinv[i];
    }
    float atr[28];
    #pragma unroll
    for (int i = 0; i < 8; i++) {
        #pragma unroll
        for (int j = i + 1; j < 8; j++) {
            int p = PIDX(i, j);
            atr[p] = ((am >> p) & 1u) ? dinv[i] * dinv[j] : 0.0f;
        }
    }
    // s_j = (1/8) * column sum of A_hat (symmetric -> row sum)
    float s[8];
    #pragma unroll
    for (int j = 0; j < 8; j++) {
        float acc = adiag[j];
        #pragma unroll
        for (int i = 0; i < 8; i++) {
            if (i != j) acc += AH(i, j);
        }
        s[j] = acc * 0.125f;
    }

    // A output (raw 0/1 adjacency, zero diagonal)
    {
        float4* ap = (float4*)(out_A + (size_t)b * 64);
        #pragma unroll
        for (int i = 0; i < 8; i++) {
            float row[8];
            #pragma unroll
            for (int j = 0; j < 8; j++) {
                if (i == j) row[j] = 0.0f;
                else {
                    int p = (i < j) ? PIDX(i, j) : PIDX(j, i);
                    row[j] = ((am >> p) & 1u) ? 1.0f : 0.0f;
                }
            }
            float4 o0 = {row[0], row[1], row[2], row[3]};
            float4 o1 = {row[4], row[5], row[6], row[7]};
            ap[2 * i]     = o0;
            ap[2 * i + 1] = o1;
        }
    }

    // ---------------- GCN: pooled = bg2 + sum_d u_d * Wg2[d][:] ----------------
    float pooled[32];
    #pragma unroll
    for (int c = 0; c < 32; c++) pooled[c] = sbg2[c];

    for (int c = 0; c < 32; c++) {
        float g0 = sg10[c], g1w = sg11[c], bgc = sbg1[c];
        float m[8];
        #pragma unroll
        for (int j = 0; j < 8; j++)
            m[j] = fmaf(px[j], g0, py[j] * g1w);

        float uc = 0.0f;
        #pragma unroll
        for (int n = 0; n < 8; n++) {
            float acc = bgc;
            #pragma unroll
            for (int j = 0; j < 8; j++)
                acc = fmaf(AH(n, j), m[j], acc);
            uc = fmaf(s[n], fmaxf(acc, 0.0f), uc);
        }

        const float4* wrow = (const float4*)(sWg2 + c * 32);
        #pragma unroll
        for (int q = 0; q < 8; q++) {
            float4 w = wrow[q];
            pooled[4 * q]     = fmaf(uc, w.x, pooled[4 * q]);
            pooled[4 * q + 1] = fmaf(uc, w.y, pooled[4 * q + 1]);
            pooled[4 * q + 2] = fmaf(uc, w.z, pooled[4 * q + 2]);
            pooled[4 * q + 3] = fmaf(uc, w.w, pooled[4 * q + 3]);
        }
    }

    // ---------------- decoder -> recon scalar ----------------
    float recon = sbd2;
    for (int e = 0; e < 64; e++) {
        float acc = sbd1[e];
        const float4* wr = (const float4*)(sWd1T + e * 32);
        #pragma unroll
        for (int q = 0; q < 8; q++) {
            float4 w = wr[q];
            acc = fmaf(pooled[4 * q],     w.x, acc);
            acc = fmaf(pooled[4 * q + 1], w.y, acc);
            acc = fmaf(pooled[4 * q + 2], w.z, acc);
            acc = fmaf(pooled[4 * q + 3], w.w, acc);
        }
        recon = fmaf(fmaxf(acc, 0.0f), swd2[e], recon);
    }

    {
        float4 r4 = {recon, recon, recon, recon};
        float4* rp = (float4*)(out_recon + (size_t)b * 8);
        rp[0] = r4;
        rp[1] = r4;
    }
}

extern "C" void kernel_launch(void* const* d_in, const int* in_sizes, int n_in,
                              void* d_out, int out_size)
{
    const float* x     = (const float*)d_in[0];
    const float* noise = (const float*)d_in[1];
    const float* We1   = (const float*)d_in[2];
    const float* be1   = (const float*)d_in[3];
    const float* We2   = (const float*)d_in[4];
    const float* be2   = (const float*)d_in[5];
    const float* Wg1   = (const float*)d_in[6];
    const float* bg1   = (const float*)d_in[7];
    const float* Wg2   = (const float*)d_in[8];
    const float* bg2   = (const float*)d_in[9];
    const float* Wd1   = (const float*)d_in[10];
    const float* bd1   = (const float*)d_in[11];
    const float* Wd2   = (const float*)d_in[12];
    const float* bd2   = (const float*)d_in[13];

    const int nb = in_sizes[0] / NN;
    float* out = (float*)d_out;

    dim3 grid((nb + BLOCK - 1) / BLOCK);
    gae_kernel<<<grid, BLOCK>>>(x, noise, We1, be1, We2, be2, Wg1, bg1,
                                Wg2, bg2, Wd1, bd1, Wd2, bd2, out, nb);
}

// round 2
// speedup vs baseline: 1.2342x; 1.2342x over previous
#include <cuda_runtime.h>
#include <cstdint>

// One thread per batch. Weights staged in shared memory (broadcast LDS).
// f32x2 packed math (FFMA2) on all recon-path GEMM-like loops.
// Lat/Gabriel path kept bit-identical to round-1 kernel (rel_err preservation).
// Output layout: [recon (nb*8)] [lat (nb*16)] [A (nb*64)]

constexpr int NN = 8;
constexpr int BLOCK = 128;

using u64 = unsigned long long;

__device__ __forceinline__ u64 pk(float lo, float hi) {
    u64 r; asm("mov.b64 %0, {%1,%2};" : "=l"(r) : "f"(lo), "f"(hi)); return r;
}
__device__ __forceinline__ void upk(u64 v, float& lo, float& hi) {
    asm("mov.b64 {%0,%1}, %2;" : "=f"(lo), "=f"(hi) : "l"(v));
}
__device__ __forceinline__ u64 fma2(u64 a, u64 b, u64 c) {
    u64 d; asm("fma.rn.f32x2 %0, %1, %2, %3;" : "=l"(d) : "l"(a), "l"(b), "l"(c)); return d;
}
__device__ __forceinline__ u64 add2(u64 a, u64 b) {
    u64 d; asm("add.rn.f32x2 %0, %1, %2;" : "=l"(d) : "l"(a), "l"(b)); return d;
}
__device__ __forceinline__ u64 dup2(float v) { return pk(v, v); }
__device__ __forceinline__ u64 relu2(u64 v) {
    float a, b; upk(v, a, b);
    return pk(fmaxf(a, 0.0f), fmaxf(b, 0.0f));
}

__device__ __forceinline__ constexpr int PIDX(int i, int j) { // i<j, 0..27
    return i * 7 - (i * (i - 1)) / 2 + (j - i - 1);
}

#define AH(i, j) ((i) == (j) ? adiag[(i)] \
    : atr[PIDX(((i) < (j) ? (i) : (j)), ((i) < (j) ? (j) : (i)))])

__global__ void __launch_bounds__(BLOCK)
gae_kernel(const float* __restrict__ x, const float* __restrict__ noise,
           const float* __restrict__ We1, const float* __restrict__ be1,
           const float* __restrict__ We2, const float* __restrict__ be2,
           const float* __restrict__ Wg1, const float* __restrict__ bg1,
           const float* __restrict__ Wg2, const float* __restrict__ bg2,
           const float* __restrict__ Wd1, const float* __restrict__ bd1,
           const float* __restrict__ Wd2, const float* __restrict__ bd2,
           float* __restrict__ out, int nb)
{
    __shared__ float4 sencW[64];        // (w1, we2_col0, we2_col1, 0)
    __shared__ float4 sencC[128];       // [k][2]: c_i = fmaf(i, w2, be1) i=0..7
    __shared__ float4 sWg1p[32];        // (g0, g1, bg1, 0)
    __shared__ float4 sWg2v[32 * 8];    // Wg2 rows
    __shared__ float2 sbg2p[16];
    __shared__ float4 sWd1T[64 * 8];    // transposed [e][d]
    __shared__ float2 sdecB[64];        // (bd1_e, Wd2[e][1])
    __shared__ float  sbd2;

    const int t = threadIdx.x;
    if (t < 64) {
        float w1 = We1[64 + t];
        float w2 = We1[128 + t];
        float be = be1[t];
        sencW[t] = make_float4(w1, We2[2 * t], We2[2 * t + 1], 0.0f);
        float c[8];
        #pragma unroll
        for (int i = 0; i < 8; i++) c[i] = fmaf((float)i, w2, be);
        sencC[2 * t]     = make_float4(c[0], c[1], c[2], c[3]);
        sencC[2 * t + 1] = make_float4(c[4], c[5], c[6], c[7]);
        sdecB[t] = make_float2(bd1[t], Wd2[3 * t + 1]);
    }
    if (t < 32) {
        sWg1p[t] = make_float4(Wg1[t], Wg1[32 + t], bg1[t], 0.0f);
    }
    if (t < 16) sbg2p[t] = make_float2(bg2[2 * t], bg2[2 * t + 1]);
    for (int idx = t; idx < 1024; idx += BLOCK) ((float*)sWg2v)[idx] = Wg2[idx];
    for (int idx = t; idx < 2048; idx += BLOCK) {
        int d = idx >> 6, e = idx & 63;
        ((float*)sWd1T)[e * 32 + d] = Wd1[idx];
    }
    if (t == 0) sbd2 = bd2[1];
    __syncthreads();

    const int b = blockIdx.x * BLOCK + t;
    if (b >= nb) return;

    float* out_recon = out;
    float* out_lat   = out + (size_t)nb * 8;
    float* out_A     = out + (size_t)nb * 24;

    // ---------------- encoder (packed, per-lane bit-identical to R1) --------
    u64 x2[4];
    {
        const float4* xp = (const float4*)(x + (size_t)b * 8);
        float4 a = xp[0], c = xp[1];
        x2[0] = pk(a.x, a.y); x2[1] = pk(a.z, a.w);
        x2[2] = pk(c.x, c.y); x2[3] = pk(c.z, c.w);
    }
    u64 l0p[4], l1p[4];
    const u64 z2 = pk(0.0f, 0.0f);
    #pragma unroll
    for (int q = 0; q < 4; q++) { l0p[q] = z2; l1p[q] = z2; }

    for (int k = 0; k < 64; k++) {
        float4 w  = sencW[k];
        float4 ca = sencC[2 * k];
        float4 cb = sencC[2 * k + 1];
        u64 w1d = dup2(w.x), e0d = dup2(w.y), e1d = dup2(w.z);
        u64 c2[4] = { pk(ca.x, ca.y), pk(ca.z, ca.w),
                      pk(cb.x, cb.y), pk(cb.z, cb.w) };
        #pragma unroll
        for (int q = 0; q < 4; q++) {
            u64 h = relu2(fma2(x2[q], w1d, c2[q]));
            l0p[q] = fma2(h, e0d, l0p[q]);
            l1p[q] = fma2(h, e1d, l1p[q]);
        }
    }
    float l0[8], l1[8];
    #pragma unroll
    for (int q = 0; q < 4; q++) {
        upk(l0p[q], l0[2 * q], l0[2 * q + 1]);
        upk(l1p[q], l1[2 * q], l1[2 * q + 1]);
    }

    // ---------------- center / std / noise (identical to R1) ----------------
    float mu0 = 0.0f, mu1 = 0.0f;
    #pragma unroll
    for (int i = 0; i < 8; i++) { mu0 += l0[i]; mu1 += l1[i]; }
    mu0 *= 0.125f; mu1 *= 0.125f;

    float v0 = 0.0f, v1 = 0.0f;
    #pragma unroll
    for (int i = 0; i < 8; i++) {
        float c0 = l0[i] - mu0, c1 = l1[i] - mu1;
        v0 += c0 * c0; v1 += c1 * c1;
    }
    float sc0 = 3.0f / (sqrtf(v0 * (1.0f / 7.0f)) + 1e-8f);
    float sc1 = 3.0f / (sqrtf(v1 * (1.0f / 7.0f)) + 1e-8f);

    float nz[16];
    {
        const float4* np = (const float4*)(noise + (size_t)b * 16);
        float4 q0 = np[0], q1 = np[1], q2 = np[2], q3 = np[3];
        nz[0]=q0.x; nz[1]=q0.y; nz[2]=q0.z; nz[3]=q0.w;
        nz[4]=q1.x; nz[5]=q1.y; nz[6]=q1.z; nz[7]=q1.w;
        nz[8]=q2.x; nz[9]=q2.y; nz[10]=q2.z; nz[11]=q2.w;
        nz[12]=q3.x; nz[13]=q3.y; nz[14]=q3.z; nz[15]=q3.w;
    }
    float px[8], py[8];
    #pragma unroll
    for (int i = 0; i < 8; i++) {
        px[i] = ((l0[i] - mu0) * sc0) + nz[2 * i]     * 0.05f;
        py[i] = ((l1[i] - mu1) * sc1) + nz[2 * i + 1] * 0.05f;
    }

    // lat output
    {
        float4* lp = (float4*)(out_lat + (size_t)b * 16);
        #pragma unroll
        for (int q = 0; q < 4; q++) {
            float4 o;
            o.x = px[2 * q];     o.y = py[2 * q];
            o.z = px[2 * q + 1]; o.w = py[2 * q + 1];
            lp[q] = o;
        }
    }

    // ---------------- Gabriel graph (identical to R1) ----------------
    unsigned am = 0;
    int deg[8];
    #pragma unroll
    for (int i = 0; i < 8; i++) deg[i] = 1;  // self loop

    #pragma unroll
    for (int i = 0; i < 8; i++) {
        #pragma unroll
        for (int j = i + 1; j < 8; j++) {
            float mx = (px[i] + px[j]) * 0.5f;
            float my = (py[i] + py[j]) * 0.5f;
            float dx = px[i] - mx, dy = py[i] - my;
            float r2 = dx * dx + dy * dy;
            float mind2 = 3.402823e38f;
            #pragma unroll
            for (int k = 0; k < 8; k++) {
                if (k != i && k != j) {
                    float ax = px[k] - mx, ay = py[k] - my;
                    mind2 = fminf(mind2, ax * ax + ay * ay);
                }
            }
            if (mind2 >= r2) {
                am |= (1u << PIDX(i, j));
                deg[i]++; deg[j]++;
            }
        }
    }

    float dinv[8], adiag[8];
    #pragma unroll
    for (int i = 0; i < 8; i++) {
        dinv[i]  = rsqrtf((float)deg[i]);
        adiag[i] = dinv[i] * dinv[i];
    }
    float atr[28];
    #pragma unroll
    for (int i = 0; i < 8; i++) {
        #pragma unroll
        for (int j = i + 1; j < 8; j++) {
            int p = PIDX(i, j);
            atr[p] = ((am >> p) & 1u) ? dinv[i] * dinv[j] : 0.0f;
        }
    }
    float s[8];
    #pragma unroll
    for (int j = 0; j < 8; j++) {
        float acc = adiag[j];
        #pragma unroll
        for (int i = 0; i < 8; i++) {
            if (i != j) acc += AH(i, j);
        }
        s[j] = acc * 0.125f;
    }

    // A output (raw 0/1 adjacency, zero diagonal)
    {
        float4* ap = (float4*)(out_A + (size_t)b * 64);
        #pragma unroll
        for (int i = 0; i < 8; i++) {
            float row[8];
            #pragma unroll
            for (int j = 0; j < 8; j++) {
                if (i == j) row[j] = 0.0f;
                else {
                    int p = (i < j) ? PIDX(i, j) : PIDX(j, i);
                    row[j] = ((am >> p) & 1u) ? 1.0f : 0.0f;
                }
            }
            float4 o0 = {row[0], row[1], row[2], row[3]};
            float4 o1 = {row[4], row[5], row[6], row[7]};
            ap[2 * i]     = o0;
            ap[2 * i + 1] = o1;
        }
    }

    // ---------------- GCN restructure ----------------
    // qx_n = sum_j AH(n,j) * px_j ; qy likewise (hoists A-hat out of c-loop)
    float qx[8], qy[8];
    #pragma unroll
    for (int n = 0; n < 8; n++) {
        float ax = 0.0f, ay = 0.0f;
        #pragma unroll
        for (int j = 0; j < 8; j++) {
            float a = AH(n, j);
            ax = fmaf(a, px[j], ax);
            ay = fmaf(a, py[j], ay);
        }
        qx[n] = ax; qy[n] = ay;
    }
    u64 qx2[4], qy2[4], s2[4];
    #pragma unroll
    for (int q = 0; q < 4; q++) {
        qx2[q] = pk(qx[2 * q], qx[2 * q + 1]);
        qy2[q] = pk(qy[2 * q], qy[2 * q + 1]);
        s2[q]  = pk(s[2 * q],  s[2 * q + 1]);
    }

    u64 pooled[16];
    #pragma unroll
    for (int q = 0; q < 16; q++) {
        float2 bp = sbg2p[q];
        pooled[q] = pk(bp.x, bp.y);
    }

    for (int c = 0; c < 32; c++) {
        float4 g = sWg1p[c];
        u64 g0d = dup2(g.x), g1d = dup2(g.y), bgd = dup2(g.z);
        u64 u2 = z2;
        #pragma unroll
        for (int q = 0; q < 4; q++) {
            u64 acc = fma2(qx2[q], g0d, fma2(qy2[q], g1d, bgd));
            u2 = fma2(s2[q], relu2(acc), u2);
        }
        float ua, ub; upk(u2, ua, ub);
        u64 ud = dup2(ua + ub);
        const float4* wr = &sWg2v[c * 8];
        #pragma unroll
        for (int q = 0; q < 8; q++) {
            float4 wv = wr[q];
            pooled[2 * q]     = fma2(ud, pk(wv.x, wv.y), pooled[2 * q]);
            pooled[2 * q + 1] = fma2(ud, pk(wv.z, wv.w), pooled[2 * q + 1]);
        }
    }

    // ---------------- decoder -> recon scalar ----------------
    float recon = sbd2;
    for (int e = 0; e < 64; e++) {
        float2 bp = sdecB[e];
        u64 accA = z2, accB = z2;
        const float4* wr = &sWd1T[e * 8];
        #pragma unroll
        for (int q = 0; q < 8; q++) {
            float4 wv = wr[q];
            accA = fma2(pooled[2 * q],     pk(wv.x, wv.y), accA);
            accB = fma2(pooled[2 * q + 1], pk(wv.z, wv.w), accB);
        }
        u64 acc = add2(accA, accB);
        float sa, sb; upk(acc, sa, sb);
        float pre = (sa + sb) + bp.x;
        recon = fmaf(fmaxf(pre, 0.0f), bp.y, recon);
    }

    {
        float4 r4 = {recon, recon, recon, recon};
        float4* rp = (float4*)(out_recon + (size_t)b * 8);
        rp[0] = r4;
        rp[1] = r4;
    }
}

extern "C" void kernel_launch(void* const* d_in, const int* in_sizes, int n_in,
                              void* d_out, int out_size)
{
    const float* x     = (const float*)d_in[0];
    const float* noise = (const float*)d_in[1];
    const float* We1   = (const float*)d_in[2];
    const float* be1   = (const float*)d_in[3];
    const float* We2   = (const float*)d_in[4];
    const float* be2   = (const float*)d_in[5];
    const float* Wg1   = (const float*)d_in[6];
    const float* bg1   = (const float*)d_in[7];
    const float* Wg2   = (const float*)d_in[8];
    const float* bg2   = (const float*)d_in[9];
    const float* Wd1   = (const float*)d_in[10];
    const float* bd1   = (const float*)d_in[11];
    const float* Wd2   = (const float*)d_in[12];
    const float* bd2   = (const float*)d_in[13];

    const int nb = in_sizes[0] / NN;
    float* out = (float*)d_out;

    dim3 grid((nb + BLOCK - 1) / BLOCK);
    gae_kernel<<<grid, BLOCK>>>(x, noise, We1, be1, We2, be2, Wg1, bg1,
                                Wg2, bg2, Wd1, bd1, Wd2, bd2, out, nb);
}